// round 14
// baseline (speedup 1.0000x reference)
#include <cuda_runtime.h>
#include <cstdint>

#define BATCH 512
#define N 256
constexpr float FINF = 1e30f;

// Scratch: transposed + sanitized cost matrices (128 MiB, static).
__device__ float g_P[(size_t)BATCH * N * N];

// smem index permutation: sigma(8L+t) = 32t + L -> t-strided loops conflict-free.
__device__ __forceinline__ int sig(int x) { return ((x & 7) << 5) | (x >> 3); }

// ---------------------------------------------------------------------------
// ONE fused kernel per batch: grid=512, block=256 (8 warps).
//   Phase A (256 thr): nk = count of nonzero mask words
//   Phase B (8 warps): transpose+sanitize rows i < nk into g_P[b]
//   Phase C (warp b&7): R8 rectangular JV solver, verbatim.
// The solver warp index cycles with blockIdx so co-resident blocks' solver
// warps land on DIFFERENT SMSPs (wid%4) instead of all saturating SMSP 0
// (ncu R13: issue 21.7% avg == ~87% on SMSP0 alone).
// ---------------------------------------------------------------------------
__global__ void __launch_bounds__(256) fused_kernel(
    const float* __restrict__ costs,
    const unsigned int* __restrict__ mask,
    float* __restrict__ out)
{
    const int b    = blockIdx.x;
    const int tid  = threadIdx.x;
    const int w    = tid >> 5;
    const int lane = tid & 31;
    const int sw   = b & 7;            // solver warp for this block

    __shared__ float tiles[8][32][33];  // per-warp transpose staging
    __shared__ int   nk_sh;
    __shared__ float u[N];    // sig-indexed (rows)
    __shared__ int   c4r[N];  // sig-indexed (rows)
    __shared__ int   r4c[N];  // sig-indexed (cols)
    __shared__ float shS[N];  // sig-indexed (cols)
    __shared__ int   shP[N];  // sig-indexed (cols)

    // ---- Phase A: nk (bool widened to i32 or f32: nonzero word == true) ----
    {
        int vv = (mask[b * N + tid] != 0u) ? 1 : 0;
#pragma unroll
        for (int off = 16; off; off >>= 1) vv += __shfl_xor_sync(0xffffffffu, vv, off);
        __shared__ int sred[8];
        if (lane == 0) sred[w] = vv;
        __syncthreads();
        if (tid == 0) {
            int tot = 0;
#pragma unroll
            for (int k = 0; k < 8; k++) tot += sred[k];
            nk_sh = tot;
        }
        __syncthreads();
    }
    const int nk = nk_sh;
    const float* src = costs + (size_t)b * N * N;
    float*       dst = g_P   + (size_t)b * N * N;

    // ---- Phase B: transpose+sanitize tiles with i0 < nk (8 warps, 64 tiles) ----
    for (int t = w; t < 64; t += 8) {
        int i0 = (t >> 3) * 32;          // output row block (object index)
        if (i0 >= nk) continue;
        int j0 = (t & 7) * 32;           // output col block (prediction index)
#pragma unroll 4
        for (int s = 0; s < 32; s++) {
            float x = src[(size_t)(j0 + s) * N + (i0 + lane)];  // coalesced
            unsigned bits = __float_as_uint(x);
            if ((bits & 0x7f800000u) == 0x7f800000u) x = 1e6f;  // nan or +-inf
            tiles[w][s][lane] = x;
        }
        __syncwarp();
#pragma unroll 4
        for (int s = 0; s < 32; s++) {
            dst[(size_t)(i0 + s) * N + (j0 + lane)] = tiles[w][lane][s];
        }
        __syncwarp();
    }

    // solver state init
    if (w == 0) {
#pragma unroll
        for (int t = 0; t < 8; t++) {
            int s = 32 * t + lane;       // = sig(8*lane + t)
            u[s] = 0.0f; c4r[s] = -1; r4c[s] = -1;
        }
    }
    __syncthreads();   // g_P writes + state visible block-wide

    if (w != sw) return;   // all but the solver warp done

    // ---- Phase C: R8 solver, verbatim (one warp) ----
    const float* P = dst;
    float v[8];
#pragma unroll
    for (int t = 0; t < 8; t++) v[t] = 0.0f;

    // prefetch row 0
    float4 pf0, pf1;
    if (nk > 0) {
        const float4* p4 = (const float4*)P + lane * 2;
        pf0 = p4[0]; pf1 = p4[1];
    }

    for (int cur = 0; cur < nk; ++cur) {
        float shortest[8];
        int   prow[8];
#pragma unroll
        for (int t = 0; t < 8; t++) { shortest[t] = FINF; prow[t] = -1; }
        unsigned scMask = 0, srMask = 0;
        int   i      = cur;
        float minval = 0.0f;
        int   sink;
        float4 c0 = pf0, c1 = pf1;

        while (true) {
            if ((i >> 3) == lane) srMask |= 1u << (i & 7);   // SR[i] = true
            float ui = u[sig(i)];
            float cj[8] = {c0.x, c0.y, c0.z, c0.w, c1.x, c1.y, c1.z, c1.w};

            float mk[8];
#pragma unroll
            for (int t = 0; t < 8; t++) {
                if (!((scMask >> t) & 1u)) {
                    // reference op order: ((minval + cost) - u[i]) - v[j]
                    float r = ((minval + cj[t]) - ui) - v[t];
                    if (r < shortest[t]) { shortest[t] = r; prow[t] = i; }
                    mk[t] = shortest[t];
                } else {
                    mk[t] = FINF;  // masked (SC)
                }
            }
            // per-lane min (flat FMNMX tree), first slot achieving it
            float a0 = fminf(mk[0], mk[1]), a1 = fminf(mk[2], mk[3]);
            float a2 = fminf(mk[4], mk[5]), a3 = fminf(mk[6], mk[7]);
            float m  = fminf(fminf(a0, a1), fminf(a2, a3));
            unsigned tm = 0;
#pragma unroll
            for (int t = 0; t < 8; t++) tm |= (mk[t] == m) ? (1u << t) : 0u;
            int myJ = 8 * lane + (__ffs(tm) - 1);
            // warp min value + lowest tied lane (== lowest j)
            float g = m;
#pragma unroll
            for (int off = 16; off; off >>= 1)
                g = fminf(g, __shfl_xor_sync(0xffffffffu, g, off));
            unsigned tied = __ballot_sync(0xffffffffu, m == g);
            int srcl = __ffs(tied) - 1;
            int jmin = __shfl_sync(0xffffffffu, myJ, srcl);
            minval   = __shfl_sync(0xffffffffu, m, srcl);

            if ((jmin >> 3) == lane) scMask |= 1u << (jmin & 7);  // SC[jmin]
            int nxt = r4c[sig(jmin)];
            if (nxt < 0) { sink = jmin; break; }
            i = nxt;
            const float4* q4 = (const float4*)(P + (size_t)i * N) + lane * 2;
            c0 = q4[0]; c1 = q4[1];
        }

        // prefetch next Dijkstra's first row (latency hidden by epilogue)
        if (cur + 1 < nk) {
            const float4* q4 = (const float4*)(P + (size_t)(cur + 1) * N) + lane * 2;
            pf0 = q4[0]; pf1 = q4[1];
        }

        // dump per-column state (conflict-free)
#pragma unroll
        for (int t = 0; t < 8; t++) {
            int s = 32 * t + lane;   // = sig(8*lane + t)
            shS[s] = shortest[t];
            shP[s] = prow[t];
        }
        __syncwarp();

        // dual updates (reads c4r BEFORE augmentation)
#pragma unroll
        for (int t = 0; t < 8; t++) {
            int row = 8 * lane + t;
            int s   = 32 * t + lane;  // sig(row)
            if (row == cur) {
                u[s] = u[s] + minval;
            } else if ((srMask >> t) & 1u) {
                int c = c4r[s];
                u[s]  = u[s] + (minval - shS[sig(c)]);
            }
            if ((scMask >> t) & 1u) v[t] = v[t] - (minval - shortest[t]);
        }
        __syncwarp();

        // augment along alternating path back to cur (lane 0 of solver warp)
        if (lane == 0) {
            int j = sink;
            while (true) {
                int sj = sig(j);
                int ii = shP[sj];
                r4c[sj] = ii;
                int si = sig(ii);
                int jn = c4r[si];
                c4r[si] = j;
                j = jn;
                if (ii == cur) break;
            }
        }
        __syncwarp();
    }

    // ---- Output (float32), solver warp lanes in parallel ----
    {
        float* ob = out + b * N;
        unsigned umask = 0;
        int uc = 0;
#pragma unroll
        for (int t = 0; t < 8; t++) {
            int j = 8 * lane + t;
            bool unused = (r4c[sig(j)] < 0);
            umask |= unused ? (1u << t) : 0u;
            uc += unused ? 1 : 0;
        }
        int incl = uc;
#pragma unroll
        for (int off = 1; off < 32; off <<= 1) {
            int o = __shfl_up_sync(0xffffffffu, incl, off);
            if (lane >= off) incl += o;
        }
        int pos = nk + (incl - uc);
#pragma unroll
        for (int t = 0; t < 8; t++) {
            if ((umask >> t) & 1u) ob[pos++] = (float)(8 * lane + t);
        }
#pragma unroll
        for (int t = 0; t < 8; t++) {
            int row = 8 * lane + t;
            if (row < nk) ob[row] = (float)c4r[32 * t + lane];  // c4r[sig(row)]
        }
    }
}

// ---------------------------------------------------------------------------
extern "C" void kernel_launch(void* const* d_in, const int* in_sizes, int n_in,
                              void* d_out, int out_size) {
    int ci = 0, mi = 1;
    if (n_in >= 2 && in_sizes[0] == BATCH * N && in_sizes[1] == BATCH * N * N) {
        ci = 1; mi = 0;
    }
    const float*        costs = (const float*)d_in[ci];
    const unsigned int* mask  = (const unsigned int*)d_in[mi];
    float* out = (float*)d_out;

    fused_kernel<<<BATCH, 256>>>(costs, mask, out);
}

// round 15
// speedup vs baseline: 1.0203x; 1.0203x over previous
#include <cuda_runtime.h>
#include <cstdint>

#define BATCH 512
#define N 256
constexpr float FINF = 1e30f;

// Scratch: transposed + sanitized cost matrices (128 MiB, static).
__device__ float g_P[(size_t)BATCH * N * N];
__device__ int   g_nk[BATCH];

// smem index permutation: sigma(8L+t) = 32t + L -> t-strided loops conflict-free.
__device__ __forceinline__ int sig(int x) { return ((x & 7) << 5) | (x >> 3); }

// 8-way register mux (3-level SEL tree, compile-time indexed pairs)
__device__ __forceinline__ int mux8(const int* a, int t) {
    int s0 = (t & 1) ? a[1] : a[0];
    int s1 = (t & 1) ? a[3] : a[2];
    int s2 = (t & 1) ? a[5] : a[4];
    int s3 = (t & 1) ? a[7] : a[6];
    int p0 = (t & 2) ? s1 : s0;
    int p1 = (t & 2) ? s3 : s2;
    return (t & 4) ? p1 : p0;
}

// ---------------------------------------------------------------------------
// Kernel 1: n_k[b] = count of nonzero mask words (bool widened to i32 or f32).
// ---------------------------------------------------------------------------
__global__ void nk_kernel(const unsigned int* __restrict__ mask) {
    int b = blockIdx.x;
    int t = threadIdx.x;
    int v = (mask[b * N + t] != 0u) ? 1 : 0;
#pragma unroll
    for (int off = 16; off; off >>= 1) v += __shfl_xor_sync(0xffffffffu, v, off);
    __shared__ int s[8];
    if ((t & 31) == 0) s[t >> 5] = v;
    __syncthreads();
    if (t == 0) {
        int tot = 0;
#pragma unroll
        for (int w = 0; w < 8; w++) tot += s[w];
        g_nk[b] = tot;
    }
}

// ---------------------------------------------------------------------------
// Kernel 2: P[b][i][j] = sanitize(costs[b][j][i]) for i < n_k[b] only.
// ---------------------------------------------------------------------------
__global__ void transpose_kernel(const float* __restrict__ costs) {
    __shared__ float tile[32][33];
    int b  = blockIdx.z;
    int i0 = blockIdx.x * 32;
    int nkb = g_nk[b];
    if (i0 >= nkb) return;      // rows never read by rectangular solver
    int j0 = blockIdx.y * 32;
    int tx = threadIdx.x, ty = threadIdx.y;  // 32 x 8
    const float* src = costs + (size_t)b * N * N;
    float*       dst = g_P   + (size_t)b * N * N;
#pragma unroll
    for (int s = 0; s < 32; s += 8) {
        float x = src[(size_t)(j0 + ty + s) * N + (i0 + tx)];
        unsigned bits = __float_as_uint(x);
        if ((bits & 0x7f800000u) == 0x7f800000u) x = 1e6f;  // nan or +-inf
        tile[ty + s][tx] = x;
    }
    __syncthreads();
#pragma unroll
    for (int s = 0; s < 32; s += 8) {
        int i = i0 + ty + s;
        dst[(size_t)i * N + (j0 + tx)] = tile[tx][ty + s];
    }
}

// ---------------------------------------------------------------------------
// Kernel 3: R8 solver + register-cached r4c. Each lane caches row4col for its
// 8 own columns; the pop's dependent LDS r4c[jmin] becomes a SEL-mux (hidden
// under the butterfly) + a shfl parallel to the jmin shfl. smem r4c stays
// authoritative; lanes refresh their 8 entries after each augmentation.
// ---------------------------------------------------------------------------
__global__ void __launch_bounds__(32) solve_kernel(float* __restrict__ out) {
    const int b    = blockIdx.x;
    const int lane = threadIdx.x;
    const float* P = g_P + (size_t)b * N * N;
    const int nk   = g_nk[b];

    __shared__ float u[N];    // sig-indexed (rows)
    __shared__ int   c4r[N];  // sig-indexed (rows)
    __shared__ int   r4c[N];  // sig-indexed (cols)
    __shared__ float shS[N];  // sig-indexed (cols)
    __shared__ int   shP[N];  // sig-indexed (cols)

    float v[8];
    int   r4cl[8];            // register cache of r4c for own columns
#pragma unroll
    for (int t = 0; t < 8; t++) {
        int s = 32 * t + lane;       // = sig(8*lane + t)
        u[s] = 0.0f; c4r[s] = -1; r4c[s] = -1; v[t] = 0.0f; r4cl[t] = -1;
    }
    __syncwarp();

    // prefetch row 0
    float4 pf0, pf1;
    if (nk > 0) {
        const float4* p4 = (const float4*)P + lane * 2;
        pf0 = p4[0]; pf1 = p4[1];
    }

    for (int cur = 0; cur < nk; ++cur) {
        float shortest[8];
        int   prow[8];
#pragma unroll
        for (int t = 0; t < 8; t++) { shortest[t] = FINF; prow[t] = -1; }
        unsigned scMask = 0, srMask = 0;
        int   i      = cur;
        float minval = 0.0f;
        int   sink;
        float4 c0 = pf0, c1 = pf1;

        while (true) {
            if ((i >> 3) == lane) srMask |= 1u << (i & 7);   // SR[i] = true
            float ui = u[sig(i)];
            float cj[8] = {c0.x, c0.y, c0.z, c0.w, c1.x, c1.y, c1.z, c1.w};

            float mk[8];
#pragma unroll
            for (int t = 0; t < 8; t++) {
                if (!((scMask >> t) & 1u)) {
                    // reference op order: ((minval + cost) - u[i]) - v[j]
                    float r = ((minval + cj[t]) - ui) - v[t];
                    if (r < shortest[t]) { shortest[t] = r; prow[t] = i; }
                    mk[t] = shortest[t];
                } else {
                    mk[t] = FINF;  // masked (SC)
                }
            }
            // per-lane min (flat FMNMX tree), first slot achieving it
            float a0 = fminf(mk[0], mk[1]), a1 = fminf(mk[2], mk[3]);
            float a2 = fminf(mk[4], mk[5]), a3 = fminf(mk[6], mk[7]);
            float m  = fminf(fminf(a0, a1), fminf(a2, a3));
            unsigned tm = 0;
#pragma unroll
            for (int t = 0; t < 8; t++) tm |= (mk[t] == m) ? (1u << t) : 0u;
            int tt   = __ffs(tm) - 1;
            int myJ  = 8 * lane + tt;
            int myNxt = mux8(r4cl, tt);   // r4c of my candidate (hidden work)
            // warp min value + lowest tied lane (== lowest j)
            float g = m;
#pragma unroll
            for (int off = 16; off; off >>= 1)
                g = fminf(g, __shfl_xor_sync(0xffffffffu, g, off));
            unsigned tied = __ballot_sync(0xffffffffu, m == g);
            int src  = __ffs(tied) - 1;
            int jmin = __shfl_sync(0xffffffffu, myJ, src);
            int nxt  = __shfl_sync(0xffffffffu, myNxt, src);  // replaces LDS
            minval   = __shfl_sync(0xffffffffu, m, src);

            if ((jmin >> 3) == lane) scMask |= 1u << (jmin & 7);  // SC[jmin]
            if (nxt < 0) { sink = jmin; break; }
            i = nxt;
            const float4* q4 = (const float4*)(P + (size_t)i * N) + lane * 2;
            c0 = q4[0]; c1 = q4[1];
        }

        // prefetch next Dijkstra's first row (latency hidden by epilogue)
        if (cur + 1 < nk) {
            const float4* q4 = (const float4*)(P + (size_t)(cur + 1) * N) + lane * 2;
            pf0 = q4[0]; pf1 = q4[1];
        }

        // dump per-column state (conflict-free)
#pragma unroll
        for (int t = 0; t < 8; t++) {
            int s = 32 * t + lane;   // = sig(8*lane + t)
            shS[s] = shortest[t];
            shP[s] = prow[t];
        }
        __syncwarp();

        // dual updates (reads c4r BEFORE augmentation)
#pragma unroll
        for (int t = 0; t < 8; t++) {
            int row = 8 * lane + t;
            int s   = 32 * t + lane;  // sig(row)
            if (row == cur) {
                u[s] = u[s] + minval;
            } else if ((srMask >> t) & 1u) {
                int c = c4r[s];
                u[s]  = u[s] + (minval - shS[sig(c)]);
            }
            if ((scMask >> t) & 1u) v[t] = v[t] - (minval - shortest[t]);
        }
        __syncwarp();

        // augment along alternating path back to cur (lane 0)
        if (lane == 0) {
            int j = sink;
            while (true) {
                int sj = sig(j);
                int ii = shP[sj];
                r4c[sj] = ii;
                int si = sig(ii);
                int jn = c4r[si];
                c4r[si] = j;
                j = jn;
                if (ii == cur) break;
            }
        }
        __syncwarp();

        // refresh register cache of r4c for own columns (off critical chain)
#pragma unroll
        for (int t = 0; t < 8; t++) r4cl[t] = r4c[32 * t + lane];
        __syncwarp();
    }

    // ---- Output (float32), all lanes in parallel ----
    {
        float* ob = out + b * N;
        unsigned umask = 0;
        int uc = 0;
#pragma unroll
        for (int t = 0; t < 8; t++) {
            int j = 8 * lane + t;
            bool unused = (r4c[sig(j)] < 0);
            umask |= unused ? (1u << t) : 0u;
            uc += unused ? 1 : 0;
        }
        int incl = uc;
#pragma unroll
        for (int off = 1; off < 32; off <<= 1) {
            int o = __shfl_up_sync(0xffffffffu, incl, off);
            if (lane >= off) incl += o;
        }
        int pos = nk + (incl - uc);
#pragma unroll
        for (int t = 0; t < 8; t++) {
            if ((umask >> t) & 1u) ob[pos++] = (float)(8 * lane + t);
        }
#pragma unroll
        for (int t = 0; t < 8; t++) {
            int row = 8 * lane + t;
            if (row < nk) ob[row] = (float)c4r[32 * t + lane];  // c4r[sig(row)]
        }
    }
}

// ---------------------------------------------------------------------------
extern "C" void kernel_launch(void* const* d_in, const int* in_sizes, int n_in,
                              void* d_out, int out_size) {
    int ci = 0, mi = 1;
    if (n_in >= 2 && in_sizes[0] == BATCH * N && in_sizes[1] == BATCH * N * N) {
        ci = 1; mi = 0;
    }
    const float*        costs = (const float*)d_in[ci];
    const unsigned int* mask  = (const unsigned int*)d_in[mi];
    float* out = (float*)d_out;

    nk_kernel<<<BATCH, 256>>>(mask);
    transpose_kernel<<<dim3(N / 32, N / 32, BATCH), dim3(32, 8)>>>(costs);
    solve_kernel<<<BATCH, 32>>>(out);
}

// round 17
// speedup vs baseline: 1.0412x; 1.0205x over previous
#include <cuda_runtime.h>
#include <cstdint>

#define BATCH 512
#define N 256
constexpr float FINF = 1e30f;

// Scratch: transposed + sanitized cost matrices (128 MiB, static).
__device__ float g_P[(size_t)BATCH * N * N];
__device__ int   g_nk[BATCH];

// smem index permutation: sigma(8L+t) = 32t + L -> t-strided loops conflict-free.
__device__ __forceinline__ int sig(int x) { return ((x & 7) << 5) | (x >> 3); }

// ---------------------------------------------------------------------------
// Kernel 1: n_k[b] = count of nonzero mask words (bool widened to i32 or f32).
// ---------------------------------------------------------------------------
__global__ void nk_kernel(const unsigned int* __restrict__ mask) {
    int b = blockIdx.x;
    int t = threadIdx.x;
    int v = (mask[b * N + t] != 0u) ? 1 : 0;
#pragma unroll
    for (int off = 16; off; off >>= 1) v += __shfl_xor_sync(0xffffffffu, v, off);
    __shared__ int s[8];
    if ((t & 31) == 0) s[t >> 5] = v;
    __syncthreads();
    if (t == 0) {
        int tot = 0;
#pragma unroll
        for (int w = 0; w < 8; w++) tot += s[w];
        g_nk[b] = tot;
    }
}

// ---------------------------------------------------------------------------
// Kernel 2: P[b][i][j] = sanitize(costs[b][j][i]) for i < n_k[b] only.
// Tiles whose entire output row range is >= n_k are skipped: ~half the
// traffic, and the useful P footprint (~64 MB) then fits in L2.
// ---------------------------------------------------------------------------
__global__ void transpose_kernel(const float* __restrict__ costs) {
    __shared__ float tile[32][33];
    int b  = blockIdx.z;
    int i0 = blockIdx.x * 32;
    int nkb = g_nk[b];
    if (i0 >= nkb) return;      // rows never read by rectangular solver
    int j0 = blockIdx.y * 32;
    int tx = threadIdx.x, ty = threadIdx.y;  // 32 x 8
    const float* src = costs + (size_t)b * N * N;
    float*       dst = g_P   + (size_t)b * N * N;
#pragma unroll
    for (int s = 0; s < 32; s += 8) {
        float x = src[(size_t)(j0 + ty + s) * N + (i0 + tx)];
        unsigned bits = __float_as_uint(x);
        if ((bits & 0x7f800000u) == 0x7f800000u) x = 1e6f;  // nan or +-inf
        tile[ty + s][tx] = x;
    }
    __syncthreads();
#pragma unroll
    for (int s = 0; s < 32; s += 8) {
        int i = i0 + ty + s;
        dst[(size_t)i * N + (j0 + tx)] = tile[tx][ty + s];
    }
}

// ---------------------------------------------------------------------------
// Kernel 3: one warp per batch, RECTANGULAR (n_k x N) JV shortest augmenting
// path. Lane l owns columns j = 8l..8l+7 (2x LDG.128). Lowest tied lane ==
// lowest j. smem sig()-permuted -> conflict-free t-loops. Next Dijkstra's
// first row is prefetched during the epilogue.
// ---------------------------------------------------------------------------
__global__ void __launch_bounds__(32) solve_kernel(float* __restrict__ out) {
    const int b    = blockIdx.x;
    const int lane = threadIdx.x;
    const float* P = g_P + (size_t)b * N * N;
    const int nk   = g_nk[b];

    __shared__ float u[N];    // sig-indexed (rows)
    __shared__ int   c4r[N];  // sig-indexed (rows)
    __shared__ int   r4c[N];  // sig-indexed (cols)
    __shared__ float shS[N];  // sig-indexed (cols)
    __shared__ int   shP[N];  // sig-indexed (cols)

    float v[8];
#pragma unroll
    for (int t = 0; t < 8; t++) {
        int s = 32 * t + lane;       // = sig(8*lane + t)
        u[s] = 0.0f; c4r[s] = -1; r4c[s] = -1; v[t] = 0.0f;
    }
    __syncwarp();

    // prefetch row 0
    float4 pf0, pf1;
    if (nk > 0) {
        const float4* p4 = (const float4*)P + lane * 2;
        pf0 = p4[0]; pf1 = p4[1];
    }

    for (int cur = 0; cur < nk; ++cur) {
        float shortest[8];
        int   prow[8];
#pragma unroll
        for (int t = 0; t < 8; t++) { shortest[t] = FINF; prow[t] = -1; }
        unsigned scMask = 0, srMask = 0;
        int   i      = cur;
        float minval = 0.0f;
        int   sink;
        float4 c0 = pf0, c1 = pf1;

        while (true) {
            if ((i >> 3) == lane) srMask |= 1u << (i & 7);   // SR[i] = true
            float ui = u[sig(i)];
            float cj[8] = {c0.x, c0.y, c0.z, c0.w, c1.x, c1.y, c1.z, c1.w};

            float mk[8];
#pragma unroll
            for (int t = 0; t < 8; t++) {
                if (!((scMask >> t) & 1u)) {
                    // reference op order: ((minval + cost) - u[i]) - v[j]
                    float r = ((minval + cj[t]) - ui) - v[t];
                    if (r < shortest[t]) { shortest[t] = r; prow[t] = i; }
                    mk[t] = shortest[t];
                } else {
                    mk[t] = FINF;  // masked (SC)
                }
            }
            // per-lane min (flat FMNMX tree), first slot achieving it
            float a0 = fminf(mk[0], mk[1]), a1 = fminf(mk[2], mk[3]);
            float a2 = fminf(mk[4], mk[5]), a3 = fminf(mk[6], mk[7]);
            float m  = fminf(fminf(a0, a1), fminf(a2, a3));
            unsigned tm = 0;
#pragma unroll
            for (int t = 0; t < 8; t++) tm |= (mk[t] == m) ? (1u << t) : 0u;
            int myJ = 8 * lane + (__ffs(tm) - 1);
            // warp min value + lowest tied lane (== lowest j)
            float g = m;
#pragma unroll
            for (int off = 16; off; off >>= 1)
                g = fminf(g, __shfl_xor_sync(0xffffffffu, g, off));
            unsigned tied = __ballot_sync(0xffffffffu, m == g);
            int src  = __ffs(tied) - 1;
            int jmin = __shfl_sync(0xffffffffu, myJ, src);
            minval   = __shfl_sync(0xffffffffu, m, src);

            if ((jmin >> 3) == lane) scMask |= 1u << (jmin & 7);  // SC[jmin]
            int nxt = r4c[sig(jmin)];
            if (nxt < 0) { sink = jmin; break; }
            i = nxt;
            const float4* q4 = (const float4*)(P + (size_t)i * N) + lane * 2;
            c0 = q4[0]; c1 = q4[1];
        }

        // prefetch next Dijkstra's first row (latency hidden by epilogue)
        if (cur + 1 < nk) {
            const float4* q4 = (const float4*)(P + (size_t)(cur + 1) * N) + lane * 2;
            pf0 = q4[0]; pf1 = q4[1];
        }

        // dump per-column state (conflict-free)
#pragma unroll
        for (int t = 0; t < 8; t++) {
            int s = 32 * t + lane;   // = sig(8*lane + t)
            shS[s] = shortest[t];
            shP[s] = prow[t];
        }
        __syncwarp();

        // dual updates (reads c4r BEFORE augmentation)
#pragma unroll
        for (int t = 0; t < 8; t++) {
            int row = 8 * lane + t;
            int s   = 32 * t + lane;  // sig(row)
            if (row == cur) {
                u[s] = u[s] + minval;
            } else if ((srMask >> t) & 1u) {
                int c = c4r[s];
                u[s]  = u[s] + (minval - shS[sig(c)]);
            }
            if ((scMask >> t) & 1u) v[t] = v[t] - (minval - shortest[t]);
        }
        __syncwarp();

        // augment along alternating path back to cur (lane 0)
        if (lane == 0) {
            int j = sink;
            while (true) {
                int sj = sig(j);
                int ii = shP[sj];
                r4c[sj] = ii;
                int si = sig(ii);
                int jn = c4r[si];
                c4r[si] = j;
                j = jn;
                if (ii == cur) break;
            }
        }
        __syncwarp();
    }

    // ---- Output (float32), all lanes in parallel ----
    {
        float* ob = out + b * N;
        unsigned umask = 0;
        int uc = 0;
#pragma unroll
        for (int t = 0; t < 8; t++) {
            int j = 8 * lane + t;
            bool unused = (r4c[sig(j)] < 0);
            umask |= unused ? (1u << t) : 0u;
            uc += unused ? 1 : 0;
        }
        int incl = uc;
#pragma unroll
        for (int off = 1; off < 32; off <<= 1) {
            int o = __shfl_up_sync(0xffffffffu, incl, off);
            if (lane >= off) incl += o;
        }
        int pos = nk + (incl - uc);
#pragma unroll
        for (int t = 0; t < 8; t++) {
            if ((umask >> t) & 1u) ob[pos++] = (float)(8 * lane + t);
        }
#pragma unroll
        for (int t = 0; t < 8; t++) {
            int row = 8 * lane + t;
            if (row < nk) ob[row] = (float)c4r[32 * t + lane];  // c4r[sig(row)]
        }
    }
}

// ---------------------------------------------------------------------------
extern "C" void kernel_launch(void* const* d_in, const int* in_sizes, int n_in,
                              void* d_out, int out_size) {
    int ci = 0, mi = 1;
    if (n_in >= 2 && in_sizes[0] == BATCH * N && in_sizes[1] == BATCH * N * N) {
        ci = 1; mi = 0;
    }
    const float*        costs = (const float*)d_in[ci];
    const unsigned int* mask  = (const unsigned int*)d_in[mi];
    float* out = (float*)d_out;

    nk_kernel<<<BATCH, 256>>>(mask);
    transpose_kernel<<<dim3(N / 32, N / 32, BATCH), dim3(32, 8)>>>(costs);
    solve_kernel<<<BATCH, 32>>>(out);
}